// round 2
// baseline (speedup 1.0000x reference)
#include <cuda_runtime.h>
#include <math_constants.h>

// Problem constants
#define NSL     24
#define BB      16
#define CCH     512
#define HWN     256          // H*W
#define FEAT_IN 1024
#define CLASSES 3

// Kernel 0: initialize out with bias (out is poisoned to 0xAA by the harness).
__global__ void init_kernel(const float* __restrict__ head_b,
                            float* __restrict__ out)
{
    int o = threadIdx.x;                  // 0..47
    if (o < BB * CLASSES)
        out[o] = head_b[o % CLASSES];
}

// Kernel 1 (fused): per-(b,c) reduction + head contribution via REDG.
//
// 25 tasks per CTA, 5 warps x exactly 5 tasks (static trip count -> full
// unroll -> 10 front-batched LDG.128 per warp):
//   task 0     : feat_f_map[b,c,:,:]   -> mean           (owned by warp 0)
//   tasks 1..24: oct_maps[s,b,c,:,:]   -> mean, max_s
// Tail (thread 0): for each class cl,
//   red.add out[b][cl] += ff*W[cl][c] + fo*W[cl][512+c]
__global__ __launch_bounds__(160) void fused_kernel(
    const float* __restrict__ feat_f_map,
    const float* __restrict__ oct_maps,
    const float* __restrict__ head_w,
    float* __restrict__ out)
{
    const int bc   = blockIdx.x;          // 0 .. B*C-1
    const int b    = bc >> 9;             // / 512
    const int c    = bc & (CCH - 1);      // % 512
    const int warp = threadIdx.x >> 5;    // 0..4
    const int lane = threadIdx.x & 31;

    __shared__ float s_max[5];
    __shared__ float s_ff;

    const float* ff_base = feat_f_map + (size_t)bc * HWN;

    float local_max = -CUDART_INF_F;

    #pragma unroll
    for (int i = 0; i < 5; i++) {
        const int t = warp + 5 * i;       // warp0: 0,5,10,15,20  warp4: 4,...,24
        const float* base = (t == 0)
            ? ff_base
            : oct_maps + (((size_t)(t - 1) * BB + b) * CCH + c) * HWN;
        const float4* p = (const float4*)base;
        float4 v0 = p[lane];              // floats [4*lane .. 4*lane+3]
        float4 v1 = p[lane + 32];         // floats [128+4*lane ..]
        float s = (v0.x + v0.y) + (v0.z + v0.w)
                + (v1.x + v1.y) + (v1.z + v1.w);
        #pragma unroll
        for (int off = 16; off; off >>= 1)
            s += __shfl_xor_sync(0xffffffffu, s, off);
        if (t == 0) {
            if (lane == 0) s_ff = s;
        } else {
            local_max = fmaxf(local_max, s);
        }
    }
    if (lane == 0) s_max[warp] = local_max;
    __syncthreads();

    if (threadIdx.x == 0) {
        float m = fmaxf(fmaxf(fmaxf(s_max[0], s_max[1]),
                              fmaxf(s_max[2], s_max[3])), s_max[4]);
        const float inv = 1.0f / (float)HWN;
        const float ff = s_ff * inv;      // feat_f[b][c]
        const float fo = m    * inv;      // feat_o[b][c] = max_s mean_HW

        float* o = out + b * CLASSES;
        #pragma unroll
        for (int cl = 0; cl < CLASSES; cl++) {
            const float* w = head_w + cl * FEAT_IN;
            atomicAdd(&o[cl], ff * w[c] + fo * w[CCH + c]);   // -> REDG
        }
    }
}

extern "C" void kernel_launch(void* const* d_in, const int* in_sizes, int n_in,
                              void* d_out, int out_size)
{
    const float* feat_f_map = (const float*)d_in[0];  // (16,512,16,16)
    const float* oct_maps   = (const float*)d_in[1];  // (24,16,512,16,16)
    const float* head_w     = (const float*)d_in[2];  // (3,1024)
    const float* head_b     = (const float*)d_in[3];  // (3,)
    float* out = (float*)d_out;                        // (16,3)

    init_kernel<<<1, 64>>>(head_b, out);
    fused_kernel<<<BB * CCH, 160>>>(feat_f_map, oct_maps, head_w, out);
}

// round 3
// speedup vs baseline: 1.1925x; 1.1925x over previous
#include <cuda_runtime.h>
#include <math_constants.h>

// Problem constants
#define NSL     24
#define BB      16
#define CCH     512
#define HWN     256          // H*W
#define FEAT_IN 1024
#define CLASSES 3
#define CG      8            // c-values per CTA (one per warp)

// Kernel 0: initialize out with bias (out is poisoned to 0xAA by the harness).
__global__ void init_kernel(const float* __restrict__ head_b,
                            float* __restrict__ out)
{
    int o = threadIdx.x;                  // 0..47
    if (o < BB * CLASSES)
        out[o] = head_b[o % CLASSES];
}

// Fused kernel: grid = B * (C/CG) = 1024 CTAs, 256 threads, one wave.
// Warp w owns channel c = cg*8 + w and streams all 25 segments (feat_f + 24
// oct slices, 1KB each) with 2x float4/lane + xor-shuffle reductions.
// Head contribution: warp lane0 -> shared acc (3 floats) -> 3 global REDG/CTA.
__global__ __launch_bounds__(256, 7) void fused_kernel(
    const float* __restrict__ feat_f_map,
    const float* __restrict__ oct_maps,
    const float* __restrict__ head_w,
    float* __restrict__ out)
{
    const int gid  = blockIdx.x;          // 0..1023
    const int b    = gid >> 6;            // / 64
    const int cg   = gid & 63;            // % 64
    const int warp = threadIdx.x >> 5;    // 0..7
    const int lane = threadIdx.x & 31;
    const int c    = cg * CG + warp;      // this warp's channel

    __shared__ float s_acc[CLASSES];
    if (threadIdx.x < CLASSES) s_acc[threadIdx.x] = 0.f;
    __syncthreads();

    // feat_f segment: contiguous 1KB
    float sff;
    {
        const float4* p = (const float4*)(feat_f_map + ((size_t)(b * CCH + c) << 8));
        float4 v0 = p[lane], v1 = p[lane + 32];
        float s = (v0.x + v0.y) + (v0.z + v0.w)
                + (v1.x + v1.y) + (v1.z + v1.w);
        #pragma unroll
        for (int off = 16; off; off >>= 1)
            s += __shfl_xor_sync(0xffffffffu, s, off);
        sff = s;                          // full sum in all lanes
    }

    // 24 oct slices: max over slice means
    float vmax = -CUDART_INF_F;
    #pragma unroll 3
    for (int s = 0; s < NSL; s++) {
        const float4* p = (const float4*)
            (oct_maps + ((((size_t)s * BB + b) * CCH + c) << 8));
        float4 v0 = p[lane], v1 = p[lane + 32];
        float t = (v0.x + v0.y) + (v0.z + v0.w)
                + (v1.x + v1.y) + (v1.z + v1.w);
        #pragma unroll
        for (int off = 16; off; off >>= 1)
            t += __shfl_xor_sync(0xffffffffu, t, off);
        vmax = fmaxf(vmax, t);
    }

    // Head contribution for this c (lane 0 of each warp)
    if (lane == 0) {
        const float inv = 1.0f / (float)HWN;
        const float ff = sff  * inv;      // feat_f[b][c]
        const float fo = vmax * inv;      // feat_o[b][c] = max_s mean_HW
        #pragma unroll
        for (int cl = 0; cl < CLASSES; cl++) {
            const float* w = head_w + cl * FEAT_IN;
            atomicAdd(&s_acc[cl], ff * w[c] + fo * w[CCH + c]);
        }
    }
    __syncthreads();

    if (threadIdx.x < CLASSES)
        atomicAdd(&out[b * CLASSES + threadIdx.x], s_acc[threadIdx.x]);
}

extern "C" void kernel_launch(void* const* d_in, const int* in_sizes, int n_in,
                              void* d_out, int out_size)
{
    const float* feat_f_map = (const float*)d_in[0];  // (16,512,16,16)
    const float* oct_maps   = (const float*)d_in[1];  // (24,16,512,16,16)
    const float* head_w     = (const float*)d_in[2];  // (3,1024)
    const float* head_b     = (const float*)d_in[3];  // (3,)
    float* out = (float*)d_out;                        // (16,3)

    init_kernel<<<1, 64>>>(head_b, out);
    fused_kernel<<<BB * (CCH / CG), 256>>>(feat_f_map, oct_maps, head_w, out);
}